// round 1
// baseline (speedup 1.0000x reference)
#include <cuda_runtime.h>

// Problem constants (fixed by the dataset)
#define N_ELEMS        26214400
#define N_GRIDS        1048576      // N_ELEMS / 25
#define TPB            256
#define GRIDS_PER_BLK  TPB          // one grid per thread
#define ELEMS_PER_BLK  (TPB * 25)   // 6400
#define N_BLOCKS       (N_GRIDS / GRIDS_PER_BLK)  // 4096

// Scratch for block partials (allocation-free: __device__ globals)
__device__ float g_abs[N_BLOCKS];
__device__ int   g_dup[N_BLOCKS];
__device__ int   g_oob[N_BLOCKS];

__global__ __launch_bounds__(TPB) void pass1(const float* __restrict__ preds,
                                             const int*   __restrict__ targets) {
    __shared__ float sp[ELEMS_PER_BLK];           // 25600 B
    const int tid  = threadIdx.x;
    const long base = (long)blockIdx.x * ELEMS_PER_BLK;

    const float4* __restrict__ p4 = (const float4*)(preds + base);
    const int4*   __restrict__ t4 = (const int4*)(targets + base);
    float4* __restrict__ sp4 = (float4*)sp;

    float acc = 0.0f;
    int   oob = 0;

    // Coalesced single pass over this block's 6400 elements.
    // loss1 + oob computed inline; preds staged to smem for dup counting.
    const int n4 = ELEMS_PER_BLK / 4;             // 1600
    #pragma unroll 2
    for (int i = tid; i < n4; i += TPB) {
        float4 p = p4[i];
        int4   t = t4[i];
        acc += fabsf(p.x - (float)t.x);
        acc += fabsf(p.y - (float)t.y);
        acc += fabsf(p.z - (float)t.z);
        acc += fabsf(p.w - (float)t.w);
        oob |= (p.x < 0.5f) | (p.x > 5.5f);
        oob |= (p.y < 0.5f) | (p.y > 5.5f);
        oob |= (p.z < 0.5f) | (p.z > 5.5f);
        oob |= (p.w < 0.5f) | (p.w > 5.5f);
        sp4[i] = p;
    }
    __syncthreads();

    // Each thread owns one 5x5 grid at sp[tid*25 .. +25).
    // Stride 25 is coprime with 32 banks -> conflict-free scalar LDS.
    float a[25];
    #pragma unroll
    for (int i = 0; i < 25; i++) a[i] = sp[tid * 25 + i];

    int dup = 0;
    // Rows: element j counts if equal to any earlier k<j in the same row.
    #pragma unroll
    for (int r = 0; r < 5; r++) {
        #pragma unroll
        for (int j = 1; j < 5; j++) {
            bool d = false;
            #pragma unroll
            for (int k = 0; k < j; k++) d |= (a[5 * r + j] == a[5 * r + k]);
            dup += d;
        }
    }
    // Columns: same over transposed indexing.
    #pragma unroll
    for (int c = 0; c < 5; c++) {
        #pragma unroll
        for (int j = 1; j < 5; j++) {
            bool d = false;
            #pragma unroll
            for (int k = 0; k < j; k++) d |= (a[5 * j + c] == a[5 * k + c]);
            dup += d;
        }
    }

    // Block reduction: warp shuffle, then across the 8 warps via smem.
    #pragma unroll
    for (int off = 16; off > 0; off >>= 1) {
        acc += __shfl_down_sync(0xffffffff, acc, off);
        dup += __shfl_down_sync(0xffffffff, dup, off);
        oob |= __shfl_down_sync(0xffffffff, oob, off);
    }
    __shared__ float wabs[8];
    __shared__ int   wdup[8];
    __shared__ int   woob[8];
    if ((tid & 31) == 0) {
        wabs[tid >> 5] = acc;
        wdup[tid >> 5] = dup;
        woob[tid >> 5] = oob;
    }
    __syncthreads();
    if (tid == 0) {
        float ba = 0.0f; int bd = 0, bo = 0;
        #pragma unroll
        for (int w = 0; w < 8; w++) { ba += wabs[w]; bd += wdup[w]; bo |= woob[w]; }
        g_abs[blockIdx.x] = ba;
        g_dup[blockIdx.x] = bd;
        g_oob[blockIdx.x] = bo;
    }
}

__global__ __launch_bounds__(1024) void pass2(float* __restrict__ out) {
    __shared__ float sa[1024];
    __shared__ int   sd[1024];
    __shared__ int   so[1024];
    const int tid = threadIdx.x;

    float a = 0.0f; int d = 0, o = 0;
    // 4096 partials / 1024 threads = 4 each (fixed order -> deterministic)
    #pragma unroll
    for (int i = tid; i < N_BLOCKS; i += 1024) {
        a += g_abs[i];
        d += g_dup[i];
        o |= g_oob[i];
    }
    sa[tid] = a; sd[tid] = d; so[tid] = o;
    __syncthreads();
    #pragma unroll
    for (int s = 512; s > 0; s >>= 1) {
        if (tid < s) {
            sa[tid] += sa[tid + s];
            sd[tid] += sd[tid + s];
            so[tid] |= so[tid + s];
        }
        __syncthreads();
    }
    if (tid == 0) {
        float loss1 = sa[0] * (1.0f / (float)N_ELEMS);
        float loss2 = ((float)sd[0] / (float)N_GRIDS) * 0.1f;
        out[0] = loss1 + loss2 + (so[0] ? 1000.0f : 0.0f);
    }
}

extern "C" void kernel_launch(void* const* d_in, const int* in_sizes, int n_in,
                              void* d_out, int out_size) {
    const float* preds   = (const float*)d_in[0];
    const int*   targets = (const int*)d_in[1];
    float*       out     = (float*)d_out;

    pass1<<<N_BLOCKS, TPB>>>(preds, targets);
    pass2<<<1, 1024>>>(out);
}

// round 2
// speedup vs baseline: 1.0468x; 1.0468x over previous
#include <cuda_runtime.h>

// Problem constants (fixed by the dataset)
#define N_ELEMS        26214400
#define N_GRIDS        1048576              // N_ELEMS / 25
#define TPB            256
#define ELEMS_PER_BLK  (TPB * 25)           // 6400 floats per block
#define VEC_PER_BLK    (ELEMS_PER_BLK / 4)  // 1600 float4
#define N_BLOCKS       (N_GRIDS / TPB)      // 4096
#define ITERS          7                    // ceil(1600 / 256)
#define FIX_SCALE      1048576.0            // 2^20 fixed-point scale for loss1

// Deterministic accumulators (zero-initialized at module load; the last
// block of every launch resets them to zero, so the invariant holds across
// the correctness run and every graph replay).
__device__ unsigned long long g_sum  = 0;   // fixed-point sum of |p - t|
__device__ int                g_dup  = 0;
__device__ int                g_oob  = 0;
__device__ unsigned int       g_done = 0;

__global__ __launch_bounds__(TPB, 8) void fused_loss(
    const float* __restrict__ preds,
    const int*   __restrict__ targets,
    float*       __restrict__ out)
{
    __shared__ float sp[ELEMS_PER_BLK];     // 25600 B
    const int  tid  = threadIdx.x;
    const long base = (long)blockIdx.x * ELEMS_PER_BLK;

    const float4* __restrict__ p4 = (const float4*)(preds + base);
    const int4*   __restrict__ t4 = (const int4*)(targets + base);
    float4* sp4 = (float4*)sp;

    // ---- Load phase: front-batch all global loads (high MLP), streaming ----
    float4 p[ITERS];
    int4   t[ITERS];
    #pragma unroll
    for (int j = 0; j < ITERS; j++) {
        const int i = tid + j * TPB;
        if (i < VEC_PER_BLK) {
            p[j] = __ldcs(p4 + i);
            t[j] = __ldcs(t4 + i);
        }
    }

    // ---- Consume: loss1 accumulation, min/max for oob, stage preds to smem ----
    float acc = 0.0f;
    float mn  =  1e30f;
    float mx  = -1e30f;
    #pragma unroll
    for (int j = 0; j < ITERS; j++) {
        const int i = tid + j * TPB;
        if (i < VEC_PER_BLK) {
            const float4 pp = p[j];
            const int4   tt = t[j];
            acc += fabsf(pp.x - (float)tt.x);
            acc += fabsf(pp.y - (float)tt.y);
            acc += fabsf(pp.z - (float)tt.z);
            acc += fabsf(pp.w - (float)tt.w);
            mn = fminf(mn, fminf(fminf(pp.x, pp.y), fminf(pp.z, pp.w)));
            mx = fmaxf(mx, fmaxf(fmaxf(pp.x, pp.y), fmaxf(pp.z, pp.w)));
            sp4[i] = pp;
        }
    }
    int oob = (mn < 0.5f) | (mx > 5.5f);
    __syncthreads();

    // ---- Duplicate counting: thread tid owns grid tid (stride 25 is coprime
    //      with 32 banks -> conflict-free scalar LDS) ----
    float a[25];
    #pragma unroll
    for (int i = 0; i < 25; i++) a[i] = sp[tid * 25 + i];

    int dup = 0;
    #pragma unroll
    for (int r = 0; r < 5; r++) {
        #pragma unroll
        for (int j = 1; j < 5; j++) {
            bool d = false;
            #pragma unroll
            for (int k = 0; k < j; k++) d |= (a[5 * r + j] == a[5 * r + k]);
            dup += d;
        }
    }
    #pragma unroll
    for (int c = 0; c < 5; c++) {
        #pragma unroll
        for (int j = 1; j < 5; j++) {
            bool d = false;
            #pragma unroll
            for (int k = 0; k < j; k++) d |= (a[5 * j + c] == a[5 * k + c]);
            dup += d;
        }
    }

    // ---- Block reduction: warp shuffles, then across the 8 warps ----
    #pragma unroll
    for (int off = 16; off > 0; off >>= 1) {
        acc += __shfl_down_sync(0xffffffff, acc, off);
        dup += __shfl_down_sync(0xffffffff, dup, off);
        oob |= __shfl_down_sync(0xffffffff, oob, off);
    }
    __shared__ float wabs[8];
    __shared__ int   wdup[8];
    __shared__ int   woob[8];
    __shared__ bool  is_last;
    if ((tid & 31) == 0) {
        wabs[tid >> 5] = acc;
        wdup[tid >> 5] = dup;
        woob[tid >> 5] = oob;
    }
    __syncthreads();

    if (tid == 0) {
        float ba = 0.0f; int bd = 0, bo = 0;
        #pragma unroll
        for (int w = 0; w < 8; w++) { ba += wabs[w]; bd += wdup[w]; bo |= woob[w]; }

        // Deterministic accumulation: fixed-point integer atomics only.
        unsigned long long q = (unsigned long long)llrint((double)ba * FIX_SCALE);
        atomicAdd(&g_sum, q);
        atomicAdd(&g_dup, bd);
        if (bo) atomicOr(&g_oob, 1);
        __threadfence();
        unsigned int prev = atomicAdd(&g_done, 1u);
        is_last = (prev == (unsigned int)(gridDim.x - 1));
    }
    __syncthreads();

    // ---- Last block finalizes and self-resets globals for the next replay ----
    if (is_last && tid == 0) {
        unsigned long long s = atomicAdd(&g_sum, 0ULL);   // all writers fenced
        int td = atomicAdd(&g_dup, 0);
        int to = atomicOr(&g_oob, 0);

        double loss1 = (double)s / (FIX_SCALE * (double)N_ELEMS);
        double loss2 = ((double)td / (double)N_GRIDS) * 0.1;
        out[0] = (float)(loss1 + loss2 + (to ? 1000.0 : 0.0));

        g_sum  = 0ULL;
        g_dup  = 0;
        g_oob  = 0;
        __threadfence();
        g_done = 0;
    }
}

extern "C" void kernel_launch(void* const* d_in, const int* in_sizes, int n_in,
                              void* d_out, int out_size) {
    const float* preds   = (const float*)d_in[0];
    const int*   targets = (const int*)d_in[1];
    float*       out     = (float*)d_out;

    fused_loss<<<N_BLOCKS, TPB>>>(preds, targets, out);
}

// round 3
// speedup vs baseline: 1.0880x; 1.0394x over previous
#include <cuda_runtime.h>

// Problem constants (fixed by the dataset)
#define N_ELEMS        26214400
#define N_GRIDS        1048576              // N_ELEMS / 25
#define TPB            256
#define ELEMS_PER_BLK  (TPB * 25)           // 6400 floats per block
#define VEC_PER_BLK    (ELEMS_PER_BLK / 4)  // 1600 float4
#define N_BLOCKS       (N_GRIDS / TPB)      // 4096
#define ITERS          7                    // ceil(1600 / 256)
#define FIX_SCALE      1048576.0            // 2^20 fixed-point scale for loss1

// Deterministic accumulators (zero-initialized at module load; the last
// block of every launch resets them to zero, so the invariant holds across
// the correctness run and every graph replay).
__device__ unsigned long long g_sum  = 0;   // fixed-point sum of |p - t|
__device__ int                g_dup  = 0;
__device__ int                g_oob  = 0;
__device__ unsigned int       g_done = 0;

// NOTE: no minBlocks clamp — the front-batched load phase needs ~56 data
// registers; forcing 32 regs (R2) made ptxas serialize the loads.
__global__ __launch_bounds__(TPB) void fused_loss(
    const float* __restrict__ preds,
    const int*   __restrict__ targets,
    float*       __restrict__ out)
{
    __shared__ float sp[ELEMS_PER_BLK];     // 25600 B
    const int  tid  = threadIdx.x;
    const long base = (long)blockIdx.x * ELEMS_PER_BLK;

    const float4* __restrict__ p4 = (const float4*)(preds + base);
    const int4*   __restrict__ t4 = (const int4*)(targets + base);
    float4* sp4 = (float4*)sp;

    // ---- Load phase: front-batch ALL 14 global loads (MLP ~14), streaming ----
    float4 p[ITERS];
    int4   t[ITERS];
    #pragma unroll
    for (int j = 0; j < ITERS; j++) {
        const int i = tid + j * TPB;
        if (i < VEC_PER_BLK) {
            p[j] = __ldcs(p4 + i);
            t[j] = __ldcs(t4 + i);
        }
    }

    // ---- Consume: loss1 accumulation, min/max for oob, stage preds to smem ----
    float acc = 0.0f;
    float mn  =  1e30f;
    float mx  = -1e30f;
    #pragma unroll
    for (int j = 0; j < ITERS; j++) {
        const int i = tid + j * TPB;
        if (i < VEC_PER_BLK) {
            const float4 pp = p[j];
            const int4   tt = t[j];
            acc += fabsf(pp.x - (float)tt.x);
            acc += fabsf(pp.y - (float)tt.y);
            acc += fabsf(pp.z - (float)tt.z);
            acc += fabsf(pp.w - (float)tt.w);
            mn = fminf(mn, fminf(fminf(pp.x, pp.y), fminf(pp.z, pp.w)));
            mx = fmaxf(mx, fmaxf(fmaxf(pp.x, pp.y), fmaxf(pp.z, pp.w)));
            sp4[i] = pp;
        }
    }
    int oob = (mn < 0.5f) | (mx > 5.5f);
    __syncthreads();

    // ---- Duplicate counting: thread tid owns grid tid (stride 25 is coprime
    //      with 32 banks -> conflict-free scalar LDS) ----
    float a[25];
    #pragma unroll
    for (int i = 0; i < 25; i++) a[i] = sp[tid * 25 + i];

    int dup = 0;
    #pragma unroll
    for (int r = 0; r < 5; r++) {
        #pragma unroll
        for (int j = 1; j < 5; j++) {
            bool d = false;
            #pragma unroll
            for (int k = 0; k < j; k++) d |= (a[5 * r + j] == a[5 * r + k]);
            dup += d;
        }
    }
    #pragma unroll
    for (int c = 0; c < 5; c++) {
        #pragma unroll
        for (int j = 1; j < 5; j++) {
            bool d = false;
            #pragma unroll
            for (int k = 0; k < j; k++) d |= (a[5 * j + c] == a[5 * k + c]);
            dup += d;
        }
    }

    // ---- Block reduction: warp shuffles, then across the 8 warps ----
    #pragma unroll
    for (int off = 16; off > 0; off >>= 1) {
        acc += __shfl_down_sync(0xffffffff, acc, off);
        dup += __shfl_down_sync(0xffffffff, dup, off);
        oob |= __shfl_down_sync(0xffffffff, oob, off);
    }
    __shared__ float wabs[8];
    __shared__ int   wdup[8];
    __shared__ int   woob[8];
    __shared__ bool  is_last;
    if ((tid & 31) == 0) {
        wabs[tid >> 5] = acc;
        wdup[tid >> 5] = dup;
        woob[tid >> 5] = oob;
    }
    __syncthreads();

    if (tid == 0) {
        float ba = 0.0f; int bd = 0, bo = 0;
        #pragma unroll
        for (int w = 0; w < 8; w++) { ba += wabs[w]; bd += wdup[w]; bo |= woob[w]; }

        // Deterministic accumulation: fixed-point integer atomics only.
        unsigned long long q = (unsigned long long)llrint((double)ba * FIX_SCALE);
        atomicAdd(&g_sum, q);
        atomicAdd(&g_dup, bd);
        if (bo) atomicOr(&g_oob, 1);
        __threadfence();
        unsigned int prev = atomicAdd(&g_done, 1u);
        is_last = (prev == (unsigned int)(gridDim.x - 1));
    }
    __syncthreads();

    // ---- Last block finalizes and self-resets globals for the next replay ----
    if (is_last && tid == 0) {
        unsigned long long s = atomicAdd(&g_sum, 0ULL);   // all writers fenced
        int td = atomicAdd(&g_dup, 0);
        int to = atomicOr(&g_oob, 0);

        double loss1 = (double)s / (FIX_SCALE * (double)N_ELEMS);
        double loss2 = ((double)td / (double)N_GRIDS) * 0.1;
        out[0] = (float)(loss1 + loss2 + (to ? 1000.0 : 0.0));

        g_sum  = 0ULL;
        g_dup  = 0;
        g_oob  = 0;
        __threadfence();
        g_done = 0;
    }
}

extern "C" void kernel_launch(void* const* d_in, const int* in_sizes, int n_in,
                              void* d_out, int out_size) {
    const float* preds   = (const float*)d_in[0];
    const int*   targets = (const int*)d_in[1];
    float*       out     = (float*)d_out;

    fused_loss<<<N_BLOCKS, TPB>>>(preds, targets, out);
}